// round 13
// baseline (speedup 1.0000x reference)
#include <cuda_runtime.h>
#include <cstdint>

// Problem constants (from reference setup_inputs)
#define BATCH 128
#define CHAN  2048
#define PSZ   14
#define HW    196              // 14*14
#define NBOX  36

#define CT      32             // channels per block tile
#define NTHREADS 256

// Output layout: fc [B,C] | att [B,HW,C] | bu [B,R,C]
#define OFF_ATT ((size_t)BATCH * CHAN)                          // 262144
#define OFF_BU  (OFF_ATT + (size_t)BATCH * HW * CHAN)           // 51642368
#define TILE_BYTES (CT * HW * 4)                                // 25088, mult of 16

__global__ __launch_bounds__(NTHREADS, 8)   // cap regs at 32 -> keep 2048 thr/SM
void fused_pool_transpose_tma(const float* __restrict__ images,
                              const float* __restrict__ boxes,
                              float* __restrict__ out)
{
    const int b   = blockIdx.y;
    const int c0  = blockIdx.x * CT;
    const int tid = threadIdx.x;

    // Linear tile (stride HW=196) — TMA writes it directly, no padding.
    __shared__ __align__(16) float tile[CT * HW];
    __shared__ int   bx1[NBOX + 1], by1[NBOX + 1], bx2[NBOX + 1], by2[NBOX + 1];
    __shared__ float binv[NBOX + 1];
    __shared__ __align__(8) unsigned long long mbar;

    const uint32_t mbar_a = (uint32_t)__cvta_generic_to_shared(&mbar);
    const uint32_t tile_a = (uint32_t)__cvta_generic_to_shared(tile);

    // ---- mbarrier init ----
    if (tid == 0)
        asm volatile("mbarrier.init.shared.b64 [%0], 1;" :: "r"(mbar_a) : "memory");
    __syncthreads();

    // ---- TMA bulk load: images[b, c0..c0+31, :] -> tile (25088B) ----
    if (tid == 0) {
        asm volatile("mbarrier.arrive.expect_tx.shared.b64 _, [%0], %1;"
                     :: "r"(mbar_a), "r"((uint32_t)TILE_BYTES) : "memory");
        const float* src = images + ((size_t)b * CHAN + c0) * HW;
        asm volatile(
            "cp.async.bulk.shared::cta.global.mbarrier::complete_tx::bytes "
            "[%0], [%1], %2, [%3];"
            :: "r"(tile_a), "l"(src), "r"((uint32_t)TILE_BYTES), "r"(mbar_a)
            : "memory");
    }

    // ---- Phase 0: box coords, overlapped with the TMA transfer ----
    if (tid <= NBOX) {
        int x1, y1, x2, y2;
        if (tid < NBOX) {
            const float* bp = boxes + ((size_t)b * NBOX + tid) * 4;
            x1 = (int)rintf(bp[0] * (float)PSZ);
            y1 = (int)rintf(bp[1] * (float)PSZ);
            x2 = (int)rintf(bp[2] * (float)PSZ);
            y2 = (int)rintf(bp[3] * (float)PSZ);
            // degenerate-box fix (matches reference exactly)
            if (x1 == x2) {
                if (x2 < PSZ)      x2 += 1;
                else if (x1 > 0)   x1 -= 1;
            }
            if (y1 == y2) {
                if (y2 < PSZ)      y2 += 1;
                else if (y1 > 0)   y1 -= 1;
            }
        } else {
            x1 = 0; y1 = 0; x2 = PSZ; y2 = PSZ;   // fc as full-plane box
        }
        bx1[tid] = x1; by1[tid] = y1; bx2[tid] = x2; by2[tid] = y2;
        binv[tid] = 1.0f / (float)((y2 - y1) * (x2 - x1));
    }

    // ---- Wait for TMA completion (phase parity 0) ----
    {
        uint32_t done = 0;
        while (!done) {
            asm volatile(
                "{\n\t.reg .pred p;\n\t"
                "mbarrier.try_wait.parity.acquire.cta.shared::cta.b64 p, [%1], %2, 0x989680;\n\t"
                "selp.b32 %0, 1, 0, p;\n\t}"
                : "=r"(done) : "r"(mbar_a), "r"(0u) : "memory");
        }
    }

    // ---- Phase 2: att transpose, fully unrolled ----
    // lane = channel; LDS.128 of 4 consecutive positions. Per 8-lane phase the
    // banks are {4j+p0..+3}, j=0..7 -> all 32 -> conflict-free. Each scalar STG
    // is one full 128B line (32 consecutive channels at one position).
    {
        const int lane = tid & 31;
        const int wid  = tid >> 5;
        const float4* trow = reinterpret_cast<const float4*>(tile + lane * HW);
        float* attb = out + OFF_ATT + (size_t)b * HW * CHAN + c0 + lane;
        // q = wid + 8m, m = 0..5 (q <= 47), plus q = 48 for wid 0
        #pragma unroll
        for (int m = 0; m < 6; ++m) {
            const int q = wid + 8 * m;
            float4 v = trow[q];
            float* o = attb + (size_t)(4 * q) * CHAN;
            __stcs(o,            v.x);
            __stcs(o + CHAN,     v.y);
            __stcs(o + 2 * CHAN, v.z);
            __stcs(o + 3 * CHAN, v.w);
        }
        if (wid == 0) {
            float4 v = trow[48];
            float* o = attb + (size_t)192 * CHAN;
            __stcs(o,            v.x);
            __stcs(o + CHAN,     v.y);
            __stcs(o + 2 * CHAN, v.z);
            __stcs(o + 3 * CHAN, v.w);
        }
    }
    __syncthreads();

    // ---- Phase 3a: in-place y-prefix, diagonal column assignment ----
    // lane = channel c, column x = (x0 + (c>>3)) mod 14 -> within each 4-lane
    // bank group the x offsets are distinct -> conflict-free.
    {
        const int c = tid & 31;
        const int k = c >> 3;
        float* tp = tile + c * HW;
        #pragma unroll
        for (int pass = 0; pass < 2; ++pass) {
            const int x0 = (tid >> 5) + pass * 8;
            if (x0 < PSZ) {
                int x = x0 + k; if (x >= PSZ) x -= PSZ;
                float* col = tp + x;
                float v[PSZ];
                #pragma unroll
                for (int y = 0; y < PSZ; ++y) v[y] = col[y * PSZ];
                #pragma unroll
                for (int y = 1; y < PSZ; ++y) v[y] += v[y - 1];
                #pragma unroll
                for (int y = 1; y < PSZ; ++y) col[y * PSZ] = v[y];
            }
        }
    }
    __syncthreads();

    // ---- Phase 3b: box means via y-prefix rows ----
    // Task permutation puts fc (w=14, the heaviest) in round 0 for balance.
    // Rotated start per lane-quad (two linear segments, no per-iter wrap check)
    // breaks the 4-way same-x bank conflict.
    for (int t = tid; t < (NBOX + 1) * 32; t += NTHREADS) {
        const int wt = t >> 5;
        const int r  = (wt == 0) ? NBOX : wt - 1;   // fc first
        const int c  = t & 31;
        const int k  = c >> 3;
        const float* tp = tile + c * HW;
        const int x1 = bx1[r];
        const int w  = bx2[r] - x1;
        const int y1 = by1[r], y2 = by2[r];
        const float* bot = tp + (y2 - 1) * PSZ + x1;

        int k0 = k;                        // k mod w, k <= 3
        if (k0 >= w) k0 -= w;
        if (k0 >= w) k0 -= w;
        if (k0 >= w) k0 -= w;

        float s = 0.0f;
        if (y1 > 0) {
            const float* top = tp + (y1 - 1) * PSZ + x1;
            for (int i = k0; i < w; ++i) s += bot[i] - top[i];
            for (int i = 0; i < k0; ++i) s += bot[i] - top[i];
        } else {
            for (int i = k0; i < w; ++i) s += bot[i];
            for (int i = 0; i < k0; ++i) s += bot[i];
        }
        float* dst = (r < NBOX)
            ? (out + OFF_BU + ((size_t)b * NBOX + r) * CHAN + c0 + c)
            : (out + (size_t)b * CHAN + c0 + c);
        __stcs(dst, s * binv[r]);
    }
}

extern "C" void kernel_launch(void* const* d_in, const int* in_sizes, int n_in,
                              void* d_out, int out_size)
{
    const float* images = (const float*)d_in[0];
    const float* boxes  = (const float*)d_in[1];
    float* out = (float*)d_out;

    dim3 grid(CHAN / CT, BATCH);   // (64, 128) = 8192 blocks
    fused_pool_transpose_tma<<<grid, NTHREADS>>>(images, boxes, out);
}

// round 14
// speedup vs baseline: 1.0270x; 1.0270x over previous
#include <cuda_runtime.h>
#include <cstdint>

// Problem constants (from reference setup_inputs)
#define BATCH 128
#define CHAN  2048
#define PSZ   14
#define HW    196              // 14*14
#define NBOX  36

#define CT      32             // channels per block tile
#define NTHREADS 256

// Output layout: fc [B,C] | att [B,HW,C] | bu [B,R,C]
#define OFF_ATT ((size_t)BATCH * CHAN)                          // 262144
#define OFF_BU  (OFF_ATT + (size_t)BATCH * HW * CHAN)           // 51642368
#define TILE_BYTES (CT * HW * 4)                                // 25088, mult of 16

__global__ __launch_bounds__(NTHREADS)
void fused_pool_transpose_tma(const float* __restrict__ images,
                              const float* __restrict__ boxes,
                              float* __restrict__ out)
{
    const int b   = blockIdx.y;
    const int c0  = blockIdx.x * CT;
    const int tid = threadIdx.x;

    // Linear tile (stride HW=196) — TMA writes it directly, no padding.
    __shared__ __align__(16) float tile[CT * HW];
    __shared__ int   bx1[NBOX + 1], by1[NBOX + 1], bx2[NBOX + 1], by2[NBOX + 1];
    __shared__ float binv[NBOX + 1];
    __shared__ __align__(8) unsigned long long mbar;

    const uint32_t mbar_a = (uint32_t)__cvta_generic_to_shared(&mbar);
    const uint32_t tile_a = (uint32_t)__cvta_generic_to_shared(tile);

    // ---- mbarrier init ----
    if (tid == 0)
        asm volatile("mbarrier.init.shared.b64 [%0], 1;" :: "r"(mbar_a) : "memory");
    __syncthreads();

    // ---- TMA bulk load: images[b, c0..c0+31, :] -> tile (25088B) ----
    if (tid == 0) {
        asm volatile("mbarrier.arrive.expect_tx.shared.b64 _, [%0], %1;"
                     :: "r"(mbar_a), "r"((uint32_t)TILE_BYTES) : "memory");
        const float* src = images + ((size_t)b * CHAN + c0) * HW;
        asm volatile(
            "cp.async.bulk.shared::cta.global.mbarrier::complete_tx::bytes "
            "[%0], [%1], %2, [%3];"
            :: "r"(tile_a), "l"(src), "r"((uint32_t)TILE_BYTES), "r"(mbar_a)
            : "memory");
    }

    // ---- Phase 0: box coords, overlapped with the TMA transfer ----
    if (tid <= NBOX) {
        int x1, y1, x2, y2;
        if (tid < NBOX) {
            const float* bp = boxes + ((size_t)b * NBOX + tid) * 4;
            x1 = (int)rintf(bp[0] * (float)PSZ);
            y1 = (int)rintf(bp[1] * (float)PSZ);
            x2 = (int)rintf(bp[2] * (float)PSZ);
            y2 = (int)rintf(bp[3] * (float)PSZ);
            // degenerate-box fix (matches reference exactly)
            if (x1 == x2) {
                if (x2 < PSZ)      x2 += 1;
                else if (x1 > 0)   x1 -= 1;
            }
            if (y1 == y2) {
                if (y2 < PSZ)      y2 += 1;
                else if (y1 > 0)   y1 -= 1;
            }
        } else {
            x1 = 0; y1 = 0; x2 = PSZ; y2 = PSZ;   // fc as full-plane box
        }
        bx1[tid] = x1; by1[tid] = y1; bx2[tid] = x2; by2[tid] = y2;
        binv[tid] = 1.0f / (float)((y2 - y1) * (x2 - x1));
    }

    // ---- Wait for TMA completion (phase parity 0; acquire per thread) ----
    {
        uint32_t done = 0;
        while (!done) {
            asm volatile(
                "{\n\t.reg .pred p;\n\t"
                "mbarrier.try_wait.parity.acquire.cta.shared::cta.b64 p, [%1], %2, 0x989680;\n\t"
                "selp.b32 %0, 1, 0, p;\n\t}"
                : "=r"(done) : "r"(mbar_a), "r"(0u) : "memory");
        }
    }

    // ---- Phase 2: att transpose (R12 form — measured best) ----
    // Per lane: LDS.128 of (channel = lane, positions 4q..4q+3); conflict-free
    // (per 8-lane phase banks = {4j+4q..+3} -> all 32). Each scalar STG is one
    // full 128B line (32 consecutive channels at one position).
    {
        const int lane = tid & 31;
        const int wid  = tid >> 5;
        const float4* trow = reinterpret_cast<const float4*>(tile + lane * HW);
        float* attb = out + OFF_ATT + (size_t)b * HW * CHAN + c0 + lane;
        for (int q = wid; q < HW / 4; q += 8) {        // 49 quads over 8 warps
            float4 v = trow[q];
            float* o = attb + (size_t)(4 * q) * CHAN;
            __stcs(o,            v.x);
            __stcs(o + CHAN,     v.y);
            __stcs(o + 2 * CHAN, v.z);
            __stcs(o + 3 * CHAN, v.w);
        }
    }
    __syncthreads();

    // ---- Phase 3a: in-place y-prefix, float2 column pairs, single pass ----
    // lane = channel c (a = c>>3), column-pair j = (wid + a) mod 7, x = 2j.
    // addr = c*196 + 14y + 2j (8B aligned). Banks per 16-lane LDS.64 phase:
    // 4b + 2a + const -> 16 distinct -> conflict-free. Packed add.rn.f32x2
    // for the prefix chain. Warps 0..6 active (7 pair-tasks), warp 7 idle.
    {
        const int c = tid & 31;
        const int a = c >> 3;
        const int j0 = tid >> 5;
        if (j0 < 7) {
            int j = j0 + a; if (j >= 7) j -= 7;
            float2* col = reinterpret_cast<float2*>(tile + c * HW + 2 * j);
            // running packed prefix: s += col[y]; col[y] = s
            double s_, v_;                       // 64-bit containers for f32x2
            unsigned long long s, v;
            s = *reinterpret_cast<unsigned long long*>(&col[0]);
            #pragma unroll
            for (int y = 1; y < PSZ; ++y) {
                v = *reinterpret_cast<unsigned long long*>(&col[y * (PSZ / 2)]);
                asm("add.rn.f32x2 %0, %1, %2;" : "=l"(s) : "l"(s), "l"(v));
                *reinterpret_cast<unsigned long long*>(&col[y * (PSZ / 2)]) = s;
            }
            (void)s_; (void)v_;
        }
    }
    __syncthreads();

    // ---- Phase 3b: box means via y-prefix rows (R12 form — measured best) ----
    // Warp-uniform r, lane = channel. Rotated x-start per lane-quad breaks the
    // 4-way same-x bank conflict.
    for (int t = tid; t < (NBOX + 1) * 32; t += NTHREADS) {
        const int r = t >> 5;
        const int c = t & 31;
        const int k = c >> 3;
        const float* tp = tile + c * HW;
        const int x1 = bx1[r];
        const int w  = bx2[r] - x1;
        const int y1 = by1[r], y2 = by2[r];
        const float* bot = tp + (y2 - 1) * PSZ + x1;

        int idx = k;                       // rotate start by lane quad, mod w
        if (idx >= w) idx -= w;
        if (idx >= w) idx -= w;
        if (idx >= w) idx -= w;

        float s = 0.0f;
        if (y1 > 0) {
            const float* top = tp + (y1 - 1) * PSZ + x1;
            for (int i = 0; i < w; ++i) {
                s += bot[idx] - top[idx];
                ++idx; if (idx == w) idx = 0;
            }
        } else {
            for (int i = 0; i < w; ++i) {
                s += bot[idx];
                ++idx; if (idx == w) idx = 0;
            }
        }
        float* dst = (r < NBOX)
            ? (out + OFF_BU + ((size_t)b * NBOX + r) * CHAN + c0 + c)
            : (out + (size_t)b * CHAN + c0 + c);
        __stcs(dst, s * binv[r]);
    }
}

extern "C" void kernel_launch(void* const* d_in, const int* in_sizes, int n_in,
                              void* d_out, int out_size)
{
    const float* images = (const float*)d_in[0];
    const float* boxes  = (const float*)d_in[1];
    float* out = (float*)d_out;

    dim3 grid(CHAN / CT, BATCH);   // (64, 128) = 8192 blocks
    fused_pool_transpose_tma<<<grid, NTHREADS>>>(images, boxes, out);
}